// round 7
// baseline (speedup 1.0000x reference)
#include <cuda_runtime.h>
#include <math.h>
#include <stdint.h>

// Problem constants
#define BATCH 8
#define MCH   63
#define HW    307200
#define NBLK  80          // stats blocks per batch
#define CHUNK 3840        // HW / NBLK
#define SUB   1280
#define NSUB  3
#define PPT   5           // 256*5 = 1280
#define NV    16

// Scratch (device globals; no allocation allowed)
__device__ float g_partA[BATCH * NBLK * 4096];
__device__ float g_partX[BATCH * NBLK * 64];
__device__ float g_partS[BATCH * NBLK * 2];
__device__ float g_fit[BATCH * (4096 + 64)];   // per-batch G (lower tri, /sqrt(beta), 0 above) then w

// ---------------------------------------------------------------------------
// Kernel 1: sparse masked Gram accumulation (double-buffered gather).
// ---------------------------------------------------------------------------
__global__ void __launch_bounds__(256) stats_kernel(const float* __restrict__ bases,
                                                    const float* __restrict__ targets)
{
    const int b   = blockIdx.x / NBLK;
    const int blk = blockIdx.x % NBLK;
    const float* tgb = targets + (size_t)b * HW;
    const float* bs  = bases   + (size_t)b * MCH * HW;

    __shared__ int   pix [SUB];
    __shared__ float yls [SUB];
    __shared__ float bv  [2][NV][64];
    __shared__ float yg  [2][NV];
    __shared__ int   scan[256];

    const int tid = threadIdx.x;
    const int ti  = tid >> 4;
    const int tj  = tid & 15;

    float acc[4][4];
#pragma unroll
    for (int i = 0; i < 4; i++)
#pragma unroll
        for (int j = 0; j < 4; j++) acc[i][j] = 0.f;

    float xty = 0.f, yty = 0.f, ncnt = 0.f;

    for (int s = 0; s < NSUB; s++) {
        const int base = blk * CHUNK + s * SUB;
        const int p0   = base + tid * PPT;

        int cnt = 0;
#pragma unroll
        for (int k = 0; k < PPT; k++) {
            float y = tgb[p0 + k];
            if (isfinite(y)) cnt++;
        }
        scan[tid] = cnt;
        __syncthreads();
        for (int off = 1; off < 256; off <<= 1) {
            int v = (tid >= off) ? scan[tid - off] : 0;
            __syncthreads();
            scan[tid] += v;
            __syncthreads();
        }
        int wo    = scan[tid] - cnt;
        int total = scan[255];
        __syncthreads();

#pragma unroll
        for (int k = 0; k < PPT; k++) {
            float y = tgb[p0 + k];
            if (isfinite(y)) { pix[wo] = p0 + k; yls[wo] = y; wo++; }
        }
        __syncthreads();

        if (tid == 0) ncnt += (float)total;

        const int ng = (total + NV - 1) / NV;

        if (ng > 0) {
#pragma unroll
            for (int r = 0; r < 4; r++) {
                int idx = r * 256 + tid;
                int v = idx >> 6, c = idx & 63;
                float val = 0.f;
                if (v < total)
                    val = (c == 0) ? 1.f : bs[(size_t)(c - 1) * HW + pix[v]];
                bv[0][v][c] = val;
            }
            if (tid < NV) yg[0][tid] = (tid < total) ? yls[tid] : 0.f;
        }
        __syncthreads();

        for (int g = 0; g < ng; g++) {
            const int cur = g & 1;
            if (g + 1 < ng) {
                const int nxt = cur ^ 1;
                const int bnv = (g + 1) * NV;
#pragma unroll
                for (int r = 0; r < 4; r++) {
                    int idx = r * 256 + tid;
                    int v = idx >> 6, c = idx & 63;
                    int gv = bnv + v;
                    float val = 0.f;
                    if (gv < total)
                        val = (c == 0) ? 1.f : bs[(size_t)(c - 1) * HW + pix[gv]];
                    bv[nxt][v][c] = val;
                }
                if (tid < NV) {
                    int gv = bnv + tid;
                    yg[nxt][tid] = (gv < total) ? yls[gv] : 0.f;
                }
            }

            const float4* bv4 = (const float4*)bv[cur];
#pragma unroll
            for (int v = 0; v < NV; v++) {
                float4 R = bv4[v * 16 + ti];
                float4 C = bv4[v * 16 + tj];
                acc[0][0] += R.x * C.x; acc[0][1] += R.x * C.y; acc[0][2] += R.x * C.z; acc[0][3] += R.x * C.w;
                acc[1][0] += R.y * C.x; acc[1][1] += R.y * C.y; acc[1][2] += R.y * C.z; acc[1][3] += R.y * C.w;
                acc[2][0] += R.z * C.x; acc[2][1] += R.z * C.y; acc[2][2] += R.z * C.z; acc[2][3] += R.z * C.w;
                acc[3][0] += R.w * C.x; acc[3][1] += R.w * C.y; acc[3][2] += R.w * C.z; acc[3][3] += R.w * C.w;
            }
            if (tid < 64) {
#pragma unroll
                for (int v = 0; v < NV; v++) xty += bv[cur][v][tid] * yg[cur][v];
            }
            if (tid == 64) {
#pragma unroll
                for (int v = 0; v < NV; v++) yty += yg[cur][v] * yg[cur][v];
            }
            __syncthreads();
        }
        __syncthreads();
    }

    float* pa = g_partA + ((size_t)b * NBLK + blk) * 4096;
#pragma unroll
    for (int i = 0; i < 4; i++)
#pragma unroll
        for (int j = 0; j < 4; j++)
            pa[(ti * 4 + i) * 64 + (tj * 4 + j)] = acc[i][j];
    if (tid < 64)  g_partX[((size_t)b * NBLK + blk) * 64 + tid] = xty;
    if (tid == 64) g_partS[((size_t)b * NBLK + blk) * 2 + 0] = yty;
    if (tid == 0)  g_partS[((size_t)b * NBLK + blk) * 2 + 1] = ncnt;
}

// ---------------------------------------------------------------------------
// Kernel 2: per-batch reduce + Cholesky + solves + beta recurrence + L^-1.
// ---------------------------------------------------------------------------
__global__ void __launch_bounds__(256) solve_kernel(float* __restrict__ out)
{
    const int b   = blockIdx.x;
    const int tid = threadIdx.x;

    __shared__ float A [64 * 65];
    __shared__ float Li[64 * 65];
    __shared__ float xty[64], wv[64], zv[64];
    __shared__ float sc[4];

    for (int e = tid; e < 4096; e += 256) {
        float s = 0.f;
#pragma unroll 4
        for (int k = 0; k < NBLK; k++) s += g_partA[((size_t)b * NBLK + k) * 4096 + e];
        A[(e >> 6) * 65 + (e & 63)] = s;
    }
    if (tid < 64) {
        float s = 0.f;
#pragma unroll 4
        for (int k = 0; k < NBLK; k++) s += g_partX[((size_t)b * NBLK + k) * 64 + tid];
        xty[tid] = s;
    }
    if (tid == 0) {
        float yt = 0.f, n = 0.f;
        for (int k = 0; k < NBLK; k++) {
            yt += g_partS[((size_t)b * NBLK + k) * 2 + 0];
            n  += g_partS[((size_t)b * NBLK + k) * 2 + 1];
        }
        sc[0] = yt; sc[1] = n;
    }
    __syncthreads();

    for (int k = 0; k < 64; k++) {
        if (tid == 0) A[k * 65 + k] = sqrtf(A[k * 65 + k]);
        __syncthreads();
        if (tid > k && tid < 64) A[tid * 65 + k] /= A[k * 65 + k];
        __syncthreads();
        if (tid > k && tid < 64) {
            float l = A[tid * 65 + k];
            for (int i = k + 1; i <= tid; i++) A[tid * 65 + i] -= l * A[i * 65 + k];
        }
        __syncthreads();
    }

    if (tid < 64) zv[tid] = xty[tid];
    __syncthreads();
    for (int k = 0; k < 64; k++) {
        if (tid == k) zv[k] /= A[k * 65 + k];
        __syncthreads();
        if (tid > k && tid < 64) zv[tid] -= A[tid * 65 + k] * zv[k];
        __syncthreads();
    }
    if (tid < 64) wv[tid] = zv[tid];
    __syncthreads();
    for (int k = 63; k >= 0; k--) {
        if (tid == k) wv[k] /= A[k * 65 + k];
        __syncthreads();
        if (tid < k) wv[tid] -= A[k * 65 + tid] * wv[k];
        __syncthreads();
    }

    if (tid == 0) {
        float yt = sc[0], n = sc[1];
        float wx = 0.f, zz = 0.f;
        for (int c = 0; c < 64; c++) { wx += wv[c] * xty[c]; zz += zv[c] * zv[c]; }
        float E = yt - 2.f * wx + zz;
        float beta0 = sqrtf(n), beta = beta0;
        bool done = false;
        for (int it = 0; it < 5; it++) {
            float bn   = n / (E + 64.f / beta);
            bool  conv = fabsf(bn / beta0 - 1.f) < 0.02f;
            if (!done) { beta = bn; beta0 = bn; }
            done = done || conv;
        }
        sc[2] = beta;
    }
    __syncthreads();

    if (tid < 64) {
        const int c = tid;
        for (int k = c; k < 64; k++) {
            float s = (k == c) ? 1.f : 0.f;
            for (int j = c; j < k; j++) s -= A[k * 65 + j] * Li[j * 65 + c];
            Li[k * 65 + c] = s / A[k * 65 + k];
        }
    }
    __syncthreads();

    const float sb = rsqrtf(sc[2]);
    float* G = g_fit + (size_t)b * (4096 + 64);
    for (int e = tid; e < 4096; e += 256) {
        int i = e >> 6, j = e & 63;
        G[e] = (j <= i) ? Li[i * 65 + j] * sb : 0.f;
    }
    if (tid < 64) {
        G[4096 + tid] = wv[tid];
        out[(size_t)BATCH * HW + (size_t)b * 64 + tid] = wv[tid];
    }
}

// ---------------------------------------------------------------------------
// Kernel 3: per-pixel prediction + variance, packed f32x2 (FFMA2).
// Each thread handles TWO adjacent pixels packed in 64-bit registers.
// G staged in smem duplicated ({g,g} per element) so one broadcast LDS.128
// yields two f32x2 multipliers. pred = w.b ; var = ||G b||^2.
// ---------------------------------------------------------------------------
__device__ __forceinline__ void fma2(unsigned long long& d,
                                     unsigned long long a, unsigned long long b) {
    asm("fma.rn.f32x2 %0, %1, %2, %0;" : "+l"(d) : "l"(a), "l"(b));
}

#define ROW(I) do {                                                          \
    unsigned long long t = 0ull;                                             \
    _Pragma("unroll")                                                        \
    for (int j2 = 0; j2 <= ((I) >> 1); ++j2) {                               \
        ulonglong2 g = *(const ulonglong2*)&Gd[(I) * 64 + 2 * j2];           \
        fma2(t, g.x, bv2[2 * j2]);                                           \
        fma2(t, g.y, bv2[2 * j2 + 1]);                                       \
    }                                                                        \
    fma2(var2, t, t);                                                        \
} while (0)

#define ROW4(I) ROW(I); ROW((I) + 1); ROW((I) + 2); ROW((I) + 3)

__global__ void __launch_bounds__(256) pred_kernel(const float* __restrict__ bases,
                                                   float* __restrict__ out)
{
    const int blocks_per_batch = HW / 512;   // 600 (512 pixels per block)
    const int b   = blockIdx.x / blocks_per_batch;
    const int blk = blockIdx.x % blocks_per_batch;

    __shared__ unsigned long long Gd[4096];  // 32 KB: duplicated G
    __shared__ unsigned long long wsd[64];   // duplicated w

    const float* fit = g_fit + (size_t)b * (4096 + 64);
    for (int e = threadIdx.x; e < 4096; e += 256) {
        unsigned int u = __float_as_uint(fit[e]);
        Gd[e] = (unsigned long long)u | ((unsigned long long)u << 32);
    }
    if (threadIdx.x < 64) {
        unsigned int u = __float_as_uint(fit[4096 + threadIdx.x]);
        wsd[threadIdx.x] = (unsigned long long)u | ((unsigned long long)u << 32);
    }
    __syncthreads();

    const float* bs = bases + (size_t)b * MCH * HW;
    const int pp = blk * 512 + threadIdx.x * 2;   // first pixel of the pair

    // basis pair in packed registers: bv2[c] = {b[pp][c], b[pp+1][c]}
    unsigned long long bv2[64];
    bv2[0] = 0x3f8000003f800000ull;   // {1.0f, 1.0f}
#pragma unroll
    for (int c = 1; c < 64; c++)
        bv2[c] = *(const unsigned long long*)(bs + (size_t)(c - 1) * HW + pp);

    // prediction (packed)
    unsigned long long pred2 = 0ull;
#pragma unroll
    for (int c = 0; c < 64; c++) fma2(pred2, wsd[c], bv2[c]);

    // variance: || G b ||^2, triangular rows fully unrolled (packed)
    unsigned long long var2 = 0ull;
    ROW4(0);  ROW4(4);  ROW4(8);  ROW4(12);
    ROW4(16); ROW4(20); ROW4(24); ROW4(28);
    ROW4(32); ROW4(36); ROW4(40); ROW4(44);
    ROW4(48); ROW4(52); ROW4(56); ROW4(60);

    // both pixels are adjacent -> single 8-byte stores
    *(unsigned long long*)(out + (size_t)b * HW + pp) = pred2;
    *(unsigned long long*)(out + (size_t)BATCH * HW + (size_t)BATCH * 64
                               + (size_t)b * HW + pp) = var2;
}

// ---------------------------------------------------------------------------
extern "C" void kernel_launch(void* const* d_in, const int* in_sizes, int n_in,
                              void* d_out, int out_size)
{
    const float* bases   = (const float*)d_in[0];
    const float* targets = (const float*)d_in[1];
    if (n_in >= 2 && in_sizes[0] < in_sizes[1]) {
        const float* t = bases; bases = targets; targets = t;
    }
    float* out = (float*)d_out;

    stats_kernel<<<BATCH * NBLK, 256>>>(bases, targets);
    solve_kernel<<<BATCH, 256>>>(out);
    pred_kernel<<<BATCH * (HW / 512), 256>>>(bases, out);
}